// round 2
// baseline (speedup 1.0000x reference)
#include <cuda_runtime.h>
#include <cuda_bf16.h>

// Problem constants
#define B_  8
#define C_  128
#define H_  64
#define W_  64
#define HW_ (H_ * W_)
#define KS  7
#define PAD 3
#define NP  (KS * KS)   // 49 neighborhood offsets

// Scratch for q, k, v in (B, HW, C) channel-contiguous layout
__device__ float g_q[B_ * HW_ * C_];
__device__ float g_k[B_ * HW_ * C_];
__device__ float g_v[B_ * HW_ * C_];

// ---------------------------------------------------------------------------
// Kernel 1: q/k/v = W @ x + b  (per-batch GEMM: M=128 oc, N=64-px tile, K=128)
// grid = (B*HW/64, 3), block = 256 threads
// thread tile: 8 out-channels x 4 pixels; output layout (B, HW, C)
// ---------------------------------------------------------------------------
__global__ __launch_bounds__(256) void qkv_gemm(
    const float* __restrict__ x,
    const float* __restrict__ Wq, const float* __restrict__ bq,
    const float* __restrict__ Wk, const float* __restrict__ bk,
    const float* __restrict__ Wv, const float* __restrict__ bv)
{
    __shared__ __align__(16) float Wt[16][132];   // W^T chunk: [k][o], padded
    __shared__ __align__(16) float Xs[16][64];    // x chunk:   [k][p]

    const float* Wm;
    const float* bias;
    float* out;
    if (blockIdx.y == 0)      { Wm = Wq; bias = bq; out = g_q; }
    else if (blockIdx.y == 1) { Wm = Wk; bias = bk; out = g_k; }
    else                      { Wm = Wv; bias = bv; out = g_v; }

    const int t   = blockIdx.x;
    const int b   = t >> 6;           // 64 pixel-tiles per batch image
    const int hw0 = (t & 63) << 6;    // 64 pixels per tile
    const float* xb = x + (size_t)b * C_ * HW_;

    const int og = threadIdx.x & 15;   // out-channel group (varies fastest -> coalesced stores)
    const int pg = threadIdx.x >> 4;   // pixel group
    const int p0 = pg * 4;
    const int o0 = og * 8;

    float acc[8][4];
#pragma unroll
    for (int i = 0; i < 8; ++i)
#pragma unroll
        for (int j = 0; j < 4; ++j) acc[i][j] = 0.f;

    for (int kk = 0; kk < C_; kk += 16) {
        __syncthreads();
        // load W chunk (2048 floats), store transposed
#pragma unroll
        for (int r = 0; r < 8; ++r) {
            int i  = threadIdx.x + 256 * r;
            int cl = i & 15;
            int o  = i >> 4;
            Wt[cl][o] = Wm[o * C_ + kk + cl];
        }
        // load X chunk (1024 floats)
#pragma unroll
        for (int r = 0; r < 4; ++r) {
            int i  = threadIdx.x + 256 * r;
            int pp = i & 63;
            int kl = i >> 6;
            Xs[kl][pp] = xb[(size_t)(kk + kl) * HW_ + hw0 + pp];
        }
        __syncthreads();

#pragma unroll
        for (int k = 0; k < 16; ++k) {
            float4 w0 = *(const float4*)&Wt[k][o0];
            float4 w1 = *(const float4*)&Wt[k][o0 + 4];
            float4 xv = *(const float4*)&Xs[k][p0];
            float wv[8] = {w0.x, w0.y, w0.z, w0.w, w1.x, w1.y, w1.z, w1.w};
            float xs4[4] = {xv.x, xv.y, xv.z, xv.w};
#pragma unroll
            for (int i = 0; i < 8; ++i)
#pragma unroll
                for (int j = 0; j < 4; ++j)
                    acc[i][j] += wv[i] * xs4[j];
        }
    }

    // epilogue: add bias, write (B, HW, C) channel-contiguous
    float4 b0 = *(const float4*)&bias[o0];
    float4 b1 = *(const float4*)&bias[o0 + 4];
#pragma unroll
    for (int j = 0; j < 4; ++j) {
        float4 r0 = make_float4(acc[0][j] + b0.x, acc[1][j] + b0.y,
                                acc[2][j] + b0.z, acc[3][j] + b0.w);
        float4 r1 = make_float4(acc[4][j] + b1.x, acc[5][j] + b1.y,
                                acc[6][j] + b1.z, acc[7][j] + b1.w);
        float* dst = out + ((size_t)b * HW_ + hw0 + p0 + j) * C_ + o0;
        *(float4*)dst       = r0;
        *(float4*)(dst + 4) = r1;
    }
}

// ---------------------------------------------------------------------------
// Kernel 2: local attention.
// Tile: 16x8 pixels, 256 threads: 2 threads per pixel (tz = channel half).
// Channels staged 8 at a time (halo in smem as 2 x float4 per position).
// 49 partial logits in registers per thread; cross-half reduce + softmax via smem.
// grid = (W/16, H/8, B), block = 256
// ---------------------------------------------------------------------------
#define TW 16
#define TH 8
#define NPX (TW * TH)
#define HXW (TW + 6)
#define HXH (TH + 6)

__global__ __launch_bounds__(256, 3) void local_attn(float* __restrict__ out)
{
    __shared__ __align__(16) float4 s_halo[HXH][HXW][2];  // 8-channel halo chunk
    __shared__ float s_attn[NPX][NP];                     // exchange / attn weights

    const int px = threadIdx.x & (NPX - 1);
    const int tz = threadIdx.x >> 7;          // channel half: 0 or 1
    const int tx = px & (TW - 1);
    const int ty = px >> 4;
    const int x0 = blockIdx.x * TW;
    const int y0 = blockIdx.y * TH;
    const int b  = blockIdx.z;
    const int gx = x0 + tx;
    const int gy = y0 + ty;

    const float* qb = g_q + (size_t)b * HW_ * C_;
    const float* kb = g_k + (size_t)b * HW_ * C_;
    const float* vb = g_v + (size_t)b * HW_ * C_;

    float logits[NP];
#pragma unroll
    for (int p = 0; p < NP; ++p) logits[p] = 0.f;

    // ---- Pass 1: partial logits over this thread's 64 channels ----
    for (int c0 = 0; c0 < C_; c0 += 8) {
        __syncthreads();
        for (int i = threadIdx.x; i < HXH * HXW * 2; i += 256) {
            int j   = i & 1;
            int pos = i >> 1;
            int hy  = pos / HXW;
            int hx  = pos - hy * HXW;
            int sy  = y0 + hy - PAD, sx = x0 + hx - PAD;
            float4 val = make_float4(0.f, 0.f, 0.f, 0.f);
            if (sy >= 0 && sy < H_ && sx >= 0 && sx < W_)
                val = *(const float4*)&kb[((size_t)sy * W_ + sx) * C_ + c0 + 4 * j];
            s_halo[hy][hx][j] = val;
        }
        __syncthreads();

        float4 qf = *(const float4*)&qb[((size_t)gy * W_ + gx) * C_ + c0 + 4 * tz];
#pragma unroll
        for (int p = 0; p < NP; ++p) {
            const int dy = p / KS, dx = p - dy * KS;
            float4 kv = s_halo[ty + dy][tx + dx][tz];
            logits[p] = fmaf(qf.x, kv.x,
                        fmaf(qf.y, kv.y,
                        fmaf(qf.z, kv.z,
                        fmaf(qf.w, kv.w, logits[p]))));
        }
    }

    // ---- cross-half reduce + softmax ----
    __syncthreads();
    if (tz) {
#pragma unroll
        for (int p = 0; p < NP; ++p) s_attn[px][p] = logits[p];
    }
    __syncthreads();
    if (!tz) {
#pragma unroll
        for (int p = 0; p < NP; ++p) logits[p] += s_attn[px][p];
        float m = logits[0];
#pragma unroll
        for (int p = 1; p < NP; ++p) m = fmaxf(m, logits[p]);
        float s = 0.f;
#pragma unroll
        for (int p = 0; p < NP; ++p) {
            logits[p] = __expf(logits[p] - m);
            s += logits[p];
        }
        const float inv = 1.f / s;
#pragma unroll
        for (int p = 0; p < NP; ++p) {
            logits[p] *= inv;
            s_attn[px][p] = logits[p];
        }
    }
    __syncthreads();
    if (tz) {
#pragma unroll
        for (int p = 0; p < NP; ++p) logits[p] = s_attn[px][p];
    }

    // ---- Pass 2: y(this thread's 64 channels) = sum_p attn[p] * v(neighbor) ----
    for (int c0 = 0; c0 < C_; c0 += 8) {
        __syncthreads();
        for (int i = threadIdx.x; i < HXH * HXW * 2; i += 256) {
            int j   = i & 1;
            int pos = i >> 1;
            int hy  = pos / HXW;
            int hx  = pos - hy * HXW;
            int sy  = y0 + hy - PAD, sx = x0 + hx - PAD;
            float4 val = make_float4(0.f, 0.f, 0.f, 0.f);
            if (sy >= 0 && sy < H_ && sx >= 0 && sx < W_)
                val = *(const float4*)&vb[((size_t)sy * W_ + sx) * C_ + c0 + 4 * j];
            s_halo[hy][hx][j] = val;
        }
        __syncthreads();

        float4 accv = make_float4(0.f, 0.f, 0.f, 0.f);
#pragma unroll
        for (int p = 0; p < NP; ++p) {
            const int dy = p / KS, dx = p - dy * KS;
            float4 vv = s_halo[ty + dy][tx + dx][tz];
            accv.x = fmaf(logits[p], vv.x, accv.x);
            accv.y = fmaf(logits[p], vv.y, accv.y);
            accv.z = fmaf(logits[p], vv.z, accv.z);
            accv.w = fmaf(logits[p], vv.w, accv.w);
        }

        // output in (B, C, H, W)
        const int c = c0 + 4 * tz;
        float* op = out + ((size_t)b * C_ + c) * HW_ + (size_t)gy * W_ + gx;
        op[0]       = accv.x;
        op[HW_]     = accv.y;
        op[2 * HW_] = accv.z;
        op[3 * HW_] = accv.w;
    }
}

// ---------------------------------------------------------------------------
extern "C" void kernel_launch(void* const* d_in, const int* in_sizes, int n_in,
                              void* d_out, int out_size)
{
    const float* x  = (const float*)d_in[0];
    const float* Wq = (const float*)d_in[1];
    const float* bq = (const float*)d_in[2];
    const float* Wk = (const float*)d_in[3];
    const float* bk = (const float*)d_in[4];
    const float* Wv = (const float*)d_in[5];
    const float* bv = (const float*)d_in[6];
    float* out = (float*)d_out;

    dim3 ggrid(B_ * HW_ / 64, 3, 1);
    qkv_gemm<<<ggrid, 256>>>(x, Wq, bq, Wk, bk, Wv, bv);

    dim3 agrid(W_ / TW, H_ / TH, B_);
    local_attn<<<agrid, 256>>>(out);
}

// round 3
// speedup vs baseline: 1.4058x; 1.4058x over previous
#include <cuda_runtime.h>
#include <cuda_bf16.h>

// Problem constants
#define B_  8
#define C_  128
#define H_  64
#define W_  64
#define HW_ (H_ * W_)
#define KS  7
#define PAD 3
#define NP  (KS * KS)   // 49 neighborhood offsets

// Scratch for q, k, v in (B, HW, C) channel-contiguous layout
__device__ float g_q[B_ * HW_ * C_];
__device__ float g_k[B_ * HW_ * C_];
__device__ float g_v[B_ * HW_ * C_];

// ---------------------------------------------------------------------------
// Kernel 1: q/k/v = W @ x + b  (per-batch GEMM: M=128 oc, N=64-px tile, K=128)
// grid = (B*HW/64, 3), block = 256 threads
// thread tile: 8 out-channels x 4 pixels; output layout (B, HW, C)
// Round-1 conflict-free mapping: og = tid>>4 (Wt broadcast), pg = tid&15.
// ---------------------------------------------------------------------------
__global__ __launch_bounds__(256) void qkv_gemm(
    const float* __restrict__ x,
    const float* __restrict__ Wq, const float* __restrict__ bq,
    const float* __restrict__ Wk, const float* __restrict__ bk,
    const float* __restrict__ Wv, const float* __restrict__ bv)
{
    __shared__ __align__(16) float Wt[16][132];   // W^T chunk: [k][o], padded
    __shared__ __align__(16) float Xs[16][64];    // x chunk:   [k][p]

    const float* Wm;
    const float* bias;
    float* out;
    if (blockIdx.y == 0)      { Wm = Wq; bias = bq; out = g_q; }
    else if (blockIdx.y == 1) { Wm = Wk; bias = bk; out = g_k; }
    else                      { Wm = Wv; bias = bv; out = g_v; }

    const int t   = blockIdx.x;
    const int b   = t >> 6;           // 64 pixel-tiles per batch image
    const int hw0 = (t & 63) << 6;    // 64 pixels per tile
    const float* xb = x + (size_t)b * C_ * HW_;

    const int pg = threadIdx.x & 15;   // pixel group
    const int og = threadIdx.x >> 4;   // out-channel group (broadcast in Wt reads)
    const int p0 = pg * 4;
    const int o0 = og * 8;

    float acc[8][4];
#pragma unroll
    for (int i = 0; i < 8; ++i)
#pragma unroll
        for (int j = 0; j < 4; ++j) acc[i][j] = 0.f;

    for (int kk = 0; kk < C_; kk += 16) {
        __syncthreads();
        // load W chunk (2048 floats), store transposed
#pragma unroll
        for (int r = 0; r < 8; ++r) {
            int i  = threadIdx.x + 256 * r;
            int cl = i & 15;
            int o  = i >> 4;
            Wt[cl][o] = Wm[o * C_ + kk + cl];
        }
        // load X chunk (1024 floats)
#pragma unroll
        for (int r = 0; r < 4; ++r) {
            int i  = threadIdx.x + 256 * r;
            int pp = i & 63;
            int kl = i >> 6;
            Xs[kl][pp] = xb[(size_t)(kk + kl) * HW_ + hw0 + pp];
        }
        __syncthreads();

#pragma unroll
        for (int k = 0; k < 16; ++k) {
            float4 w0 = *(const float4*)&Wt[k][o0];
            float4 w1 = *(const float4*)&Wt[k][o0 + 4];
            float4 xv = *(const float4*)&Xs[k][p0];
            float wv[8] = {w0.x, w0.y, w0.z, w0.w, w1.x, w1.y, w1.z, w1.w};
            float xs4[4] = {xv.x, xv.y, xv.z, xv.w};
#pragma unroll
            for (int i = 0; i < 8; ++i)
#pragma unroll
                for (int j = 0; j < 4; ++j)
                    acc[i][j] = fmaf(wv[i], xs4[j], acc[i][j]);
        }
    }

    // epilogue: add bias, write (B, HW, C) channel-contiguous
    float4 b0 = *(const float4*)&bias[o0];
    float4 b1 = *(const float4*)&bias[o0 + 4];
#pragma unroll
    for (int j = 0; j < 4; ++j) {
        float4 r0 = make_float4(acc[0][j] + b0.x, acc[1][j] + b0.y,
                                acc[2][j] + b0.z, acc[3][j] + b0.w);
        float4 r1 = make_float4(acc[4][j] + b1.x, acc[5][j] + b1.y,
                                acc[6][j] + b1.z, acc[7][j] + b1.w);
        float* dst = out + ((size_t)b * HW_ + hw0 + p0 + j) * C_ + o0;
        *(float4*)dst       = r0;
        *(float4*)(dst + 4) = r1;
    }
}

// ---------------------------------------------------------------------------
// Kernel 2: local attention.
// Tile: 8x8 pixels, 256 threads: 4 threads per pixel (tg = channel quarter,
// 32 channels each). Channels staged 16 at a time (4 x float4 per position).
// Halo layout s_halo[4][14][15] -> conflict-free LDS.128 tap reads.
// grid = (8, 8, B) = 512 blocks.
// ---------------------------------------------------------------------------
#define TW 8
#define TH 8
#define NPX (TW * TH)       // 64 pixels
#define HXW (TW + 6)        // 14
#define HXH (TH + 6)        // 14
#define HPITCH 15           // padded row pitch (float4 units)

__global__ __launch_bounds__(256) void local_attn(float* __restrict__ out)
{
    __shared__ __align__(16) float4 s_halo[4][HXH][HPITCH]; // 16-channel halo chunk
    __shared__ float s_r0[NPX][53];                          // reduce / attn buf 0
    __shared__ float s_r1[NPX][53];                          // reduce buf 1

    const int px = threadIdx.x & (NPX - 1);
    const int tg = threadIdx.x >> 6;          // channel quarter: 0..3
    const int tx = px & (TW - 1);
    const int ty = px >> 3;
    const int x0 = blockIdx.x * TW;
    const int y0 = blockIdx.y * TH;
    const int b  = blockIdx.z;
    const int gx = x0 + tx;
    const int gy = y0 + ty;

    const float* qb = g_q + (size_t)b * HW_ * C_;
    const float* kb = g_k + (size_t)b * HW_ * C_;
    const float* vb = g_v + (size_t)b * HW_ * C_;

    float logits[NP];
#pragma unroll
    for (int p = 0; p < NP; ++p) logits[p] = 0.f;

    // ---- Pass 1: partial logits over this thread's 32 channels ----
    for (int c0 = 0; c0 < C_; c0 += 16) {
        __syncthreads();
        for (int i = threadIdx.x; i < HXH * HXW * 4; i += 256) {
            int j   = i & 3;            // channel sub-group (fastest -> 64B ldg)
            int pos = i >> 2;
            int hy  = pos / HXW;
            int hx  = pos - hy * HXW;
            int sy  = y0 + hy - PAD, sx = x0 + hx - PAD;
            float4 val = make_float4(0.f, 0.f, 0.f, 0.f);
            if (sy >= 0 && sy < H_ && sx >= 0 && sx < W_)
                val = *(const float4*)&kb[((size_t)sy * W_ + sx) * C_ + c0 + 4 * j];
            s_halo[j][hy][hx] = val;
        }
        __syncthreads();

        float4 qf = *(const float4*)&qb[((size_t)gy * W_ + gx) * C_ + c0 + 4 * tg];
#pragma unroll
        for (int p = 0; p < NP; ++p) {
            const int dy = p / KS, dx = p - dy * KS;
            float4 kv = s_halo[tg][ty + dy][tx + dx];
            logits[p] = fmaf(qf.x, kv.x,
                        fmaf(qf.y, kv.y,
                        fmaf(qf.z, kv.z,
                        fmaf(qf.w, kv.w, logits[p]))));
        }
    }

    // ---- cross-group reduce (4 partials) + softmax ----
    __syncthreads();
    if (tg == 2) {
#pragma unroll
        for (int p = 0; p < NP; ++p) s_r0[px][p] = logits[p];
    } else if (tg == 3) {
#pragma unroll
        for (int p = 0; p < NP; ++p) s_r1[px][p] = logits[p];
    }
    __syncthreads();
    if (tg == 0) {
#pragma unroll
        for (int p = 0; p < NP; ++p) logits[p] += s_r0[px][p];
    } else if (tg == 1) {
#pragma unroll
        for (int p = 0; p < NP; ++p) {
            logits[p] += s_r1[px][p];
            s_r1[px][p] = logits[p];
        }
    }
    __syncthreads();
    if (tg == 0) {
#pragma unroll
        for (int p = 0; p < NP; ++p) logits[p] += s_r1[px][p];
        float m = logits[0];
#pragma unroll
        for (int p = 1; p < NP; ++p) m = fmaxf(m, logits[p]);
        float s = 0.f;
#pragma unroll
        for (int p = 0; p < NP; ++p) {
            logits[p] = __expf(logits[p] - m);
            s += logits[p];
        }
        const float inv = 1.f / s;
#pragma unroll
        for (int p = 0; p < NP; ++p) {
            logits[p] *= inv;
            s_r0[px][p] = logits[p];
        }
    }
    __syncthreads();
    if (tg != 0) {
#pragma unroll
        for (int p = 0; p < NP; ++p) logits[p] = s_r0[px][p];
    }

    // ---- Pass 2: y(this thread's 32 channels) = sum_p attn[p] * v(neighbor) ----
    for (int c0 = 0; c0 < C_; c0 += 16) {
        __syncthreads();
        for (int i = threadIdx.x; i < HXH * HXW * 4; i += 256) {
            int j   = i & 3;
            int pos = i >> 2;
            int hy  = pos / HXW;
            int hx  = pos - hy * HXW;
            int sy  = y0 + hy - PAD, sx = x0 + hx - PAD;
            float4 val = make_float4(0.f, 0.f, 0.f, 0.f);
            if (sy >= 0 && sy < H_ && sx >= 0 && sx < W_)
                val = *(const float4*)&vb[((size_t)sy * W_ + sx) * C_ + c0 + 4 * j];
            s_halo[j][hy][hx] = val;
        }
        __syncthreads();

        float4 accv = make_float4(0.f, 0.f, 0.f, 0.f);
#pragma unroll
        for (int p = 0; p < NP; ++p) {
            const int dy = p / KS, dx = p - dy * KS;
            float4 vv = s_halo[tg][ty + dy][tx + dx];
            accv.x = fmaf(logits[p], vv.x, accv.x);
            accv.y = fmaf(logits[p], vv.y, accv.y);
            accv.z = fmaf(logits[p], vv.z, accv.z);
            accv.w = fmaf(logits[p], vv.w, accv.w);
        }

        // output in (B, C, H, W)
        const int c = c0 + 4 * tg;
        float* op = out + ((size_t)b * C_ + c) * HW_ + (size_t)gy * W_ + gx;
        op[0]       = accv.x;
        op[HW_]     = accv.y;
        op[2 * HW_] = accv.z;
        op[3 * HW_] = accv.w;
    }
}

// ---------------------------------------------------------------------------
extern "C" void kernel_launch(void* const* d_in, const int* in_sizes, int n_in,
                              void* d_out, int out_size)
{
    const float* x  = (const float*)d_in[0];
    const float* Wq = (const float*)d_in[1];
    const float* bq = (const float*)d_in[2];
    const float* Wk = (const float*)d_in[3];
    const float* bk = (const float*)d_in[4];
    const float* Wv = (const float*)d_in[5];
    const float* bv = (const float*)d_in[6];
    float* out = (float*)d_out;

    dim3 ggrid(B_ * HW_ / 64, 3, 1);
    qkv_gemm<<<ggrid, 256>>>(x, Wq, bq, Wk, bk, Wv, bv);

    dim3 agrid(W_ / TW, H_ / TH, B_);
    local_attn<<<agrid, 256>>>(out);
}

// round 4
// speedup vs baseline: 1.5406x; 1.0958x over previous
#include <cuda_runtime.h>
#include <cuda_fp16.h>
#include <cuda_bf16.h>

// Problem constants
#define B_  8
#define C_  128
#define H_  64
#define W_  64
#define HW_ (H_ * W_)
#define KS  7
#define PAD 3
#define NP  (KS * KS)   // 49 neighborhood offsets

// Scratch for q, k, v in (B, HW, C) channel-contiguous layout
__device__ float g_q[B_ * HW_ * C_];
__device__ float g_k[B_ * HW_ * C_];
__device__ float g_v[B_ * HW_ * C_];

// ---------------------------------------------------------------------------
// Kernel 1: q/k/v = W @ x + b  (per-batch GEMM: M=128 oc, N=64-px tile, K=128)
// grid = (B*HW/64, 3), block = 256 threads
// thread tile: 4 out-channels x 8 pixels; output layout (B, HW, C).
// og = tid&31 (o0=og*4): conflict-free Wt reads AND coalesced channel-contig stores.
// pg = tid>>5 (p0=pg*8): Xs reads are warp-broadcast.
// ---------------------------------------------------------------------------
__global__ __launch_bounds__(256) void qkv_gemm(
    const float* __restrict__ x,
    const float* __restrict__ Wq, const float* __restrict__ bq,
    const float* __restrict__ Wk, const float* __restrict__ bk,
    const float* __restrict__ Wv, const float* __restrict__ bv)
{
    __shared__ __align__(16) float Wt[16][132];   // W^T chunk: [k][o], padded
    __shared__ __align__(16) float Xs[16][64];    // x chunk:   [k][p]

    const float* Wm;
    const float* bias;
    float* out;
    if (blockIdx.y == 0)      { Wm = Wq; bias = bq; out = g_q; }
    else if (blockIdx.y == 1) { Wm = Wk; bias = bk; out = g_k; }
    else                      { Wm = Wv; bias = bv; out = g_v; }

    const int t   = blockIdx.x;
    const int b   = t >> 6;           // 64 pixel-tiles per batch image
    const int hw0 = (t & 63) << 6;    // 64 pixels per tile
    const float* xb = x + (size_t)b * C_ * HW_;

    const int og = threadIdx.x & 31;   // out-channel group (fastest)
    const int pg = threadIdx.x >> 5;   // pixel group (one per warp)
    const int o0 = og * 4;
    const int p0 = pg * 8;

    float acc[4][8];
#pragma unroll
    for (int i = 0; i < 4; ++i)
#pragma unroll
        for (int j = 0; j < 8; ++j) acc[i][j] = 0.f;

    for (int kk = 0; kk < C_; kk += 16) {
        __syncthreads();
        // load W chunk (2048 floats), store transposed
#pragma unroll
        for (int r = 0; r < 8; ++r) {
            int i  = threadIdx.x + 256 * r;
            int cl = i & 15;
            int o  = i >> 4;
            Wt[cl][o] = Wm[o * C_ + kk + cl];
        }
        // load X chunk (1024 floats)
#pragma unroll
        for (int r = 0; r < 4; ++r) {
            int i  = threadIdx.x + 256 * r;
            int pp = i & 63;
            int kl = i >> 6;
            Xs[kl][pp] = xb[(size_t)(kk + kl) * HW_ + hw0 + pp];
        }
        __syncthreads();

#pragma unroll
        for (int k = 0; k < 16; ++k) {
            float4 w4 = *(const float4*)&Wt[k][o0];
            float4 xa = *(const float4*)&Xs[k][p0];
            float4 xb4 = *(const float4*)&Xs[k][p0 + 4];
            float wv[4]  = {w4.x, w4.y, w4.z, w4.w};
            float xs8[8] = {xa.x, xa.y, xa.z, xa.w, xb4.x, xb4.y, xb4.z, xb4.w};
#pragma unroll
            for (int i = 0; i < 4; ++i)
#pragma unroll
                for (int j = 0; j < 8; ++j)
                    acc[i][j] = fmaf(wv[i], xs8[j], acc[i][j]);
        }
    }

    // epilogue: add bias, write (B, HW, C) channel-contiguous (coalesced)
    float4 bb = *(const float4*)&bias[o0];
#pragma unroll
    for (int j = 0; j < 8; ++j) {
        float4 r = make_float4(acc[0][j] + bb.x, acc[1][j] + bb.y,
                               acc[2][j] + bb.z, acc[3][j] + bb.w);
        *(float4*)&out[((size_t)b * HW_ + hw0 + p0 + j) * C_ + o0] = r;
    }
}

// ---------------------------------------------------------------------------
// Kernel 2: local attention.
// Tile: 8x8 pixels, 256 threads: 4 threads/pixel (tg = channel quarter, 32 ch).
// Channels staged 32 at a time. Halo layout [hy][j][hx] (pitch 15 float4/uint4):
//   - staging STS (j fastest across lanes, 240B stride) conflict-free
//   - tap LDS (hx fastest, 16B stride) conflict-free
// Pass 1 (logits): fp32 halo. Pass 2 (V apply): half2-packed halo (fp32 math).
// Softmax reduce buffers alias the halo smem (keeps static smem < 48KB).
// grid = (8, 8, B) = 512 blocks, 3 blocks/SM.
// ---------------------------------------------------------------------------
#define TW 8
#define TH 8
#define NPX (TW * TH)       // 64 pixels
#define HXW (TW + 6)        // 14
#define HXH (TH + 6)        // 14
#define HPITCH 15           // padded pitch (16B units)

__global__ __launch_bounds__(256, 3) void local_attn(float* __restrict__ out)
{
    // 14 * 8 * 15 * 16B = 26.25 KB, aliased three ways
    __shared__ __align__(16) char s_raw[HXH * 8 * HPITCH * 16];
    float4* hal4 = (float4*)s_raw;   // [hy][j(0..7)][hx] fp32, 4 ch per float4
    uint4*  hal2 = (uint4*)s_raw;    // [hy][j(0..3)][hx] half2, 8 ch per uint4
    float*  rbuf = (float*)s_raw;    // softmax exchange: [2][64][49]

    const int px = threadIdx.x & (NPX - 1);
    const int tg = threadIdx.x >> 6;          // channel quarter: 0..3
    const int tx = px & (TW - 1);
    const int ty = px >> 3;
    const int x0 = blockIdx.x * TW;
    const int y0 = blockIdx.y * TH;
    const int b  = blockIdx.z;
    const int gx = x0 + tx;
    const int gy = y0 + ty;

    const float* qb = g_q + (size_t)b * HW_ * C_;
    const float* kb = g_k + (size_t)b * HW_ * C_;
    const float* vb = g_v + (size_t)b * HW_ * C_;

    float logits[NP];
#pragma unroll
    for (int p = 0; p < NP; ++p) logits[p] = 0.f;

    // ---- Pass 1: partial logits over this thread's 32 channels (fp32 halo) ----
    for (int c0 = 0; c0 < C_; c0 += 32) {
        __syncthreads();
        for (int i = threadIdx.x; i < HXH * HXW * 8; i += 256) {
            int j   = i & 7;           // 4-ch sub-group (fastest -> coalesced LDG)
            int pos = i >> 3;
            int hy  = pos / HXW;
            int hx  = pos - hy * HXW;
            int sy  = y0 + hy - PAD, sx = x0 + hx - PAD;
            float4 val = make_float4(0.f, 0.f, 0.f, 0.f);
            if (sy >= 0 && sy < H_ && sx >= 0 && sx < W_)
                val = *(const float4*)&kb[((size_t)sy * W_ + sx) * C_ + c0 + 4 * j];
            hal4[((size_t)hy * 8 + j) * HPITCH + hx] = val;
        }
        __syncthreads();

        const float* qp = &qb[((size_t)gy * W_ + gx) * C_ + c0 + 8 * tg];
        float4 qf0 = *(const float4*)qp;
        float4 qf1 = *(const float4*)(qp + 4);
#pragma unroll
        for (int p = 0; p < NP; ++p) {
            const int dy = p / KS, dx = p - dy * KS;
            const size_t base = ((size_t)(ty + dy) * 8 + 2 * tg) * HPITCH + (tx + dx);
            float4 k0 = hal4[base];
            float4 k1 = hal4[base + HPITCH];
            float acc = fmaf(qf0.x, k0.x, fmaf(qf0.y, k0.y,
                        fmaf(qf0.z, k0.z, fmaf(qf0.w, k0.w, logits[p]))));
            logits[p] = fmaf(qf1.x, k1.x, fmaf(qf1.y, k1.y,
                        fmaf(qf1.z, k1.z, fmaf(qf1.w, k1.w, acc))));
        }
    }

    // ---- cross-group reduce (4 partials) + softmax (buffers alias halo smem) ----
    float* r0 = rbuf;                 // [64][49]
    float* r1 = rbuf + NPX * NP;      // [64][49]
    __syncthreads();
    if (tg == 2) {
#pragma unroll
        for (int p = 0; p < NP; ++p) r0[px * NP + p] = logits[p];
    } else if (tg == 3) {
#pragma unroll
        for (int p = 0; p < NP; ++p) r1[px * NP + p] = logits[p];
    }
    __syncthreads();
    if (tg == 0) {
#pragma unroll
        for (int p = 0; p < NP; ++p) logits[p] += r0[px * NP + p];
    } else if (tg == 1) {
#pragma unroll
        for (int p = 0; p < NP; ++p) {
            logits[p] += r1[px * NP + p];
            r1[px * NP + p] = logits[p];
        }
    }
    __syncthreads();
    if (tg == 0) {
#pragma unroll
        for (int p = 0; p < NP; ++p) logits[p] += r1[px * NP + p];
        float m = logits[0];
#pragma unroll
        for (int p = 1; p < NP; ++p) m = fmaxf(m, logits[p]);
        float s = 0.f;
#pragma unroll
        for (int p = 0; p < NP; ++p) {
            logits[p] = __expf(logits[p] - m);
            s += logits[p];
        }
        const float inv = 1.f / s;
#pragma unroll
        for (int p = 0; p < NP; ++p) {
            logits[p] *= inv;
            r0[px * NP + p] = logits[p];
        }
    }
    __syncthreads();
    if (tg != 0) {
#pragma unroll
        for (int p = 0; p < NP; ++p) logits[p] = r0[px * NP + p];
    }

    // ---- Pass 2: y(32 ch) = sum_p attn[p] * v(neighbor); half2-packed halo ----
    for (int c0 = 0; c0 < C_; c0 += 32) {
        __syncthreads();
        for (int i = threadIdx.x; i < HXH * HXW * 4; i += 256) {
            int j   = i & 3;           // 8-ch sub-group
            int pos = i >> 2;
            int hy  = pos / HXW;
            int hx  = pos - hy * HXW;
            int sy  = y0 + hy - PAD, sx = x0 + hx - PAD;
            uint4 hv = make_uint4(0u, 0u, 0u, 0u);
            if (sy >= 0 && sy < H_ && sx >= 0 && sx < W_) {
                const float* vp = &vb[((size_t)sy * W_ + sx) * C_ + c0 + 8 * j];
                float4 a = *(const float4*)vp;
                float4 c = *(const float4*)(vp + 4);
                half2 h0 = __floats2half2_rn(a.x, a.y);
                half2 h1 = __floats2half2_rn(a.z, a.w);
                half2 h2 = __floats2half2_rn(c.x, c.y);
                half2 h3 = __floats2half2_rn(c.z, c.w);
                hv.x = *(unsigned*)&h0;
                hv.y = *(unsigned*)&h1;
                hv.z = *(unsigned*)&h2;
                hv.w = *(unsigned*)&h3;
            }
            hal2[((size_t)hy * 4 + j) * HPITCH + hx] = hv;
        }
        __syncthreads();

        float acc8[8];
#pragma unroll
        for (int i = 0; i < 8; ++i) acc8[i] = 0.f;
#pragma unroll
        for (int p = 0; p < NP; ++p) {
            const int dy = p / KS, dx = p - dy * KS;
            uint4 hv = hal2[((size_t)(ty + dy) * 4 + tg) * HPITCH + (tx + dx)];
            const float w = logits[p];
            float2 f0 = __half22float2(*(half2*)&hv.x);
            float2 f1 = __half22float2(*(half2*)&hv.y);
            float2 f2 = __half22float2(*(half2*)&hv.z);
            float2 f3 = __half22float2(*(half2*)&hv.w);
            acc8[0] = fmaf(w, f0.x, acc8[0]);
            acc8[1] = fmaf(w, f0.y, acc8[1]);
            acc8[2] = fmaf(w, f1.x, acc8[2]);
            acc8[3] = fmaf(w, f1.y, acc8[3]);
            acc8[4] = fmaf(w, f2.x, acc8[4]);
            acc8[5] = fmaf(w, f2.y, acc8[5]);
            acc8[6] = fmaf(w, f3.x, acc8[6]);
            acc8[7] = fmaf(w, f3.y, acc8[7]);
        }

        // output in (B, C, H, W); this thread's channels: c0 + 8*tg .. +7
        const int c = c0 + 8 * tg;
        float* op = out + ((size_t)b * C_ + c) * HW_ + (size_t)gy * W_ + gx;
#pragma unroll
        for (int i = 0; i < 8; ++i) op[(size_t)i * HW_] = acc8[i];
    }
}

// ---------------------------------------------------------------------------
extern "C" void kernel_launch(void* const* d_in, const int* in_sizes, int n_in,
                              void* d_out, int out_size)
{
    const float* x  = (const float*)d_in[0];
    const float* Wq = (const float*)d_in[1];
    const float* bq = (const float*)d_in[2];
    const float* Wk = (const float*)d_in[3];
    const float* bk = (const float*)d_in[4];
    const float* Wv = (const float*)d_in[5];
    const float* bv = (const float*)d_in[6];
    float* out = (float*)d_out;

    dim3 ggrid(B_ * HW_ / 64, 3, 1);
    qkv_gemm<<<ggrid, 256>>>(x, Wq, bq, Wk, bk, Wv, bv);

    dim3 agrid(W_ / TW, H_ / TH, B_);
    local_attn<<<agrid, 256>>>(out);
}

// round 5
// speedup vs baseline: 1.7166x; 1.1142x over previous
#include <cuda_runtime.h>
#include <cuda_fp16.h>
#include <cuda_bf16.h>

// Problem constants
#define B_  8
#define C_  128
#define H_  64
#define W_  64
#define HW_ (H_ * W_)
#define KS  7
#define PAD 3
#define NP  (KS * KS)   // 49 neighborhood offsets

// Scratch for q, k, v in (B, HW, C) channel-contiguous layout
__device__ float g_q[B_ * HW_ * C_];
__device__ float g_k[B_ * HW_ * C_];
__device__ float g_v[B_ * HW_ * C_];

// ---- packed f32x2 helpers (Blackwell sm_100+; PTX-only, ptxas won't emit) ----
__device__ __forceinline__ void fma2(unsigned long long& d,
                                     unsigned long long a,
                                     unsigned long long b) {
    asm("fma.rn.f32x2 %0, %1, %2, %0;" : "+l"(d) : "l"(a), "l"(b));
}
__device__ __forceinline__ unsigned long long splat2(float x) {
    unsigned long long r;
    asm("mov.b64 %0, {%1, %1};" : "=l"(r) : "f"(x));
    return r;
}
__device__ __forceinline__ float2 unpack2(unsigned long long v) {
    float2 r;
    asm("mov.b64 {%0, %1}, %2;" : "=f"(r.x), "=f"(r.y) : "l"(v));
    return r;
}

// ---------------------------------------------------------------------------
// Kernel 1: q/k/v = W @ x + b  (per-batch GEMM: M=128 oc, N=64-px tile, K=128)
// grid = (B*HW/64, 3), block = 256 threads
// thread tile: 4 out-channels x 8 pixels (4 px-PAIRS via fma.rn.f32x2).
// og = tid&31 (o0=og*4): conflict-free Wt reads, coalesced (B,HW,C) stores.
// pg = tid>>5 (p0=pg*8): Xs reads warp-broadcast; px pairs free via u64 loads.
// ---------------------------------------------------------------------------
__global__ __launch_bounds__(256) void qkv_gemm(
    const float* __restrict__ x,
    const float* __restrict__ Wq, const float* __restrict__ bq,
    const float* __restrict__ Wk, const float* __restrict__ bk,
    const float* __restrict__ Wv, const float* __restrict__ bv)
{
    __shared__ __align__(16) float Wt[16][132];   // W^T chunk: [k][o], padded
    __shared__ __align__(16) float Xs[16][64];    // x chunk:   [k][p]

    const float* Wm;
    const float* bias;
    float* out;
    if (blockIdx.y == 0)      { Wm = Wq; bias = bq; out = g_q; }
    else if (blockIdx.y == 1) { Wm = Wk; bias = bk; out = g_k; }
    else                      { Wm = Wv; bias = bv; out = g_v; }

    const int t   = blockIdx.x;
    const int b   = t >> 6;           // 64 pixel-tiles per batch image
    const int hw0 = (t & 63) << 6;    // 64 pixels per tile
    const float* xb = x + (size_t)b * C_ * HW_;

    const int og = threadIdx.x & 31;   // out-channel group (fastest)
    const int pg = threadIdx.x >> 5;   // pixel group (one per warp)
    const int o0 = og * 4;
    const int p0 = pg * 8;

    // acc2[i][j] = packed (acc for px p0+2j, acc for px p0+2j+1), out-channel o0+i
    unsigned long long acc2[4][4];
#pragma unroll
    for (int i = 0; i < 4; ++i)
#pragma unroll
        for (int j = 0; j < 4; ++j) acc2[i][j] = 0ull;

    for (int kk = 0; kk < C_; kk += 16) {
        __syncthreads();
        // load W chunk (2048 floats), store transposed
#pragma unroll
        for (int r = 0; r < 8; ++r) {
            int i  = threadIdx.x + 256 * r;
            int cl = i & 15;
            int o  = i >> 4;
            Wt[cl][o] = Wm[o * C_ + kk + cl];
        }
        // load X chunk (1024 floats)
#pragma unroll
        for (int r = 0; r < 4; ++r) {
            int i  = threadIdx.x + 256 * r;
            int pp = i & 63;
            int kl = i >> 6;
            Xs[kl][pp] = xb[(size_t)(kk + kl) * HW_ + hw0 + pp];
        }
        __syncthreads();

#pragma unroll
        for (int k = 0; k < 16; ++k) {
            float4 w4 = *(const float4*)&Wt[k][o0];
            ulonglong2 xp0 = *(const ulonglong2*)&Xs[k][p0];     // px pairs 0,1
            ulonglong2 xp1 = *(const ulonglong2*)&Xs[k][p0 + 4]; // px pairs 2,3
            unsigned long long w2[4] = {splat2(w4.x), splat2(w4.y),
                                        splat2(w4.z), splat2(w4.w)};
            unsigned long long x2[4] = {xp0.x, xp0.y, xp1.x, xp1.y};
#pragma unroll
            for (int i = 0; i < 4; ++i)
#pragma unroll
                for (int j = 0; j < 4; ++j)
                    fma2(acc2[i][j], w2[i], x2[j]);
        }
    }

    // epilogue: add bias, write (B, HW, C) channel-contiguous (coalesced)
    float4 bb = *(const float4*)&bias[o0];
#pragma unroll
    for (int j = 0; j < 4; ++j) {
        float2 a0 = unpack2(acc2[0][j]);
        float2 a1 = unpack2(acc2[1][j]);
        float2 a2 = unpack2(acc2[2][j]);
        float2 a3 = unpack2(acc2[3][j]);
        float4 rlo = make_float4(a0.x + bb.x, a1.x + bb.y, a2.x + bb.z, a3.x + bb.w);
        float4 rhi = make_float4(a0.y + bb.x, a1.y + bb.y, a2.y + bb.z, a3.y + bb.w);
        *(float4*)&out[((size_t)b * HW_ + hw0 + p0 + 2 * j)     * C_ + o0] = rlo;
        *(float4*)&out[((size_t)b * HW_ + hw0 + p0 + 2 * j + 1) * C_ + o0] = rhi;
    }
}

// ---------------------------------------------------------------------------
// Kernel 2: local attention (unchanged from round 4 — 91us, isolating GEMM change).
// Tile: 8x8 pixels, 256 threads: 4 threads/pixel (tg = channel quarter, 32 ch).
// ---------------------------------------------------------------------------
#define TW 8
#define TH 8
#define NPX (TW * TH)       // 64 pixels
#define HXW (TW + 6)        // 14
#define HXH (TH + 6)        // 14
#define HPITCH 15           // padded pitch (16B units)

__global__ __launch_bounds__(256, 3) void local_attn(float* __restrict__ out)
{
    __shared__ __align__(16) char s_raw[HXH * 8 * HPITCH * 16];
    float4* hal4 = (float4*)s_raw;   // [hy][j(0..7)][hx] fp32, 4 ch per float4
    uint4*  hal2 = (uint4*)s_raw;    // [hy][j(0..3)][hx] half2, 8 ch per uint4
    float*  rbuf = (float*)s_raw;    // softmax exchange: [2][64][49]

    const int px = threadIdx.x & (NPX - 1);
    const int tg = threadIdx.x >> 6;          // channel quarter: 0..3
    const int tx = px & (TW - 1);
    const int ty = px >> 3;
    const int x0 = blockIdx.x * TW;
    const int y0 = blockIdx.y * TH;
    const int b  = blockIdx.z;
    const int gx = x0 + tx;
    const int gy = y0 + ty;

    const float* qb = g_q + (size_t)b * HW_ * C_;
    const float* kb = g_k + (size_t)b * HW_ * C_;
    const float* vb = g_v + (size_t)b * HW_ * C_;

    float logits[NP];
#pragma unroll
    for (int p = 0; p < NP; ++p) logits[p] = 0.f;

    // ---- Pass 1: partial logits over this thread's 32 channels (fp32 halo) ----
    for (int c0 = 0; c0 < C_; c0 += 32) {
        __syncthreads();
        for (int i = threadIdx.x; i < HXH * HXW * 8; i += 256) {
            int j   = i & 7;
            int pos = i >> 3;
            int hy  = pos / HXW;
            int hx  = pos - hy * HXW;
            int sy  = y0 + hy - PAD, sx = x0 + hx - PAD;
            float4 val = make_float4(0.f, 0.f, 0.f, 0.f);
            if (sy >= 0 && sy < H_ && sx >= 0 && sx < W_)
                val = *(const float4*)&kb[((size_t)sy * W_ + sx) * C_ + c0 + 4 * j];
            hal4[((size_t)hy * 8 + j) * HPITCH + hx] = val;
        }
        __syncthreads();

        const float* qp = &qb[((size_t)gy * W_ + gx) * C_ + c0 + 8 * tg];
        float4 qf0 = *(const float4*)qp;
        float4 qf1 = *(const float4*)(qp + 4);
#pragma unroll
        for (int p = 0; p < NP; ++p) {
            const int dy = p / KS, dx = p - dy * KS;
            const size_t base = ((size_t)(ty + dy) * 8 + 2 * tg) * HPITCH + (tx + dx);
            float4 k0 = hal4[base];
            float4 k1 = hal4[base + HPITCH];
            float acc = fmaf(qf0.x, k0.x, fmaf(qf0.y, k0.y,
                        fmaf(qf0.z, k0.z, fmaf(qf0.w, k0.w, logits[p]))));
            logits[p] = fmaf(qf1.x, k1.x, fmaf(qf1.y, k1.y,
                        fmaf(qf1.z, k1.z, fmaf(qf1.w, k1.w, acc))));
        }
    }

    // ---- cross-group reduce (4 partials) + softmax ----
    float* r0 = rbuf;                 // [64][49]
    float* r1 = rbuf + NPX * NP;      // [64][49]
    __syncthreads();
    if (tg == 2) {
#pragma unroll
        for (int p = 0; p < NP; ++p) r0[px * NP + p] = logits[p];
    } else if (tg == 3) {
#pragma unroll
        for (int p = 0; p < NP; ++p) r1[px * NP + p] = logits[p];
    }
    __syncthreads();
    if (tg == 0) {
#pragma unroll
        for (int p = 0; p < NP; ++p) logits[p] += r0[px * NP + p];
    } else if (tg == 1) {
#pragma unroll
        for (int p = 0; p < NP; ++p) {
            logits[p] += r1[px * NP + p];
            r1[px * NP + p] = logits[p];
        }
    }
    __syncthreads();
    if (tg == 0) {
#pragma unroll
        for (int p = 0; p < NP; ++p) logits[p] += r1[px * NP + p];
        float m = logits[0];
#pragma unroll
        for (int p = 1; p < NP; ++p) m = fmaxf(m, logits[p]);
        float s = 0.f;
#pragma unroll
        for (int p = 0; p < NP; ++p) {
            logits[p] = __expf(logits[p] - m);
            s += logits[p];
        }
        const float inv = 1.f / s;
#pragma unroll
        for (int p = 0; p < NP; ++p) {
            logits[p] *= inv;
            r0[px * NP + p] = logits[p];
        }
    }
    __syncthreads();
    if (tg != 0) {
#pragma unroll
        for (int p = 0; p < NP; ++p) logits[p] = r0[px * NP + p];
    }

    // ---- Pass 2: y(32 ch) = sum_p attn[p] * v(neighbor); half2-packed halo ----
    for (int c0 = 0; c0 < C_; c0 += 32) {
        __syncthreads();
        for (int i = threadIdx.x; i < HXH * HXW * 4; i += 256) {
            int j   = i & 3;
            int pos = i >> 2;
            int hy  = pos / HXW;
            int hx  = pos - hy * HXW;
            int sy  = y0 + hy - PAD, sx = x0 + hx - PAD;
            uint4 hv = make_uint4(0u, 0u, 0u, 0u);
            if (sy >= 0 && sy < H_ && sx >= 0 && sx < W_) {
                const float* vp = &vb[((size_t)sy * W_ + sx) * C_ + c0 + 8 * j];
                float4 a = *(const float4*)vp;
                float4 c = *(const float4*)(vp + 4);
                half2 h0 = __floats2half2_rn(a.x, a.y);
                half2 h1 = __floats2half2_rn(a.z, a.w);
                half2 h2 = __floats2half2_rn(c.x, c.y);
                half2 h3 = __floats2half2_rn(c.z, c.w);
                hv.x = *(unsigned*)&h0;
                hv.y = *(unsigned*)&h1;
                hv.z = *(unsigned*)&h2;
                hv.w = *(unsigned*)&h3;
            }
            hal2[((size_t)hy * 4 + j) * HPITCH + hx] = hv;
        }
        __syncthreads();

        float acc8[8];
#pragma unroll
        for (int i = 0; i < 8; ++i) acc8[i] = 0.f;
#pragma unroll
        for (int p = 0; p < NP; ++p) {
            const int dy = p / KS, dx = p - dy * KS;
            uint4 hv = hal2[((size_t)(ty + dy) * 4 + tg) * HPITCH + (tx + dx)];
            const float w = logits[p];
            float2 f0 = __half22float2(*(half2*)&hv.x);
            float2 f1 = __half22float2(*(half2*)&hv.y);
            float2 f2 = __half22float2(*(half2*)&hv.z);
            float2 f3 = __half22float2(*(half2*)&hv.w);
            acc8[0] = fmaf(w, f0.x, acc8[0]);
            acc8[1] = fmaf(w, f0.y, acc8[1]);
            acc8[2] = fmaf(w, f1.x, acc8[2]);
            acc8[3] = fmaf(w, f1.y, acc8[3]);
            acc8[4] = fmaf(w, f2.x, acc8[4]);
            acc8[5] = fmaf(w, f2.y, acc8[5]);
            acc8[6] = fmaf(w, f3.x, acc8[6]);
            acc8[7] = fmaf(w, f3.y, acc8[7]);
        }

        const int c = c0 + 8 * tg;
        float* op = out + ((size_t)b * C_ + c) * HW_ + (size_t)gy * W_ + gx;
#pragma unroll
        for (int i = 0; i < 8; ++i) op[(size_t)i * HW_] = acc8[i];
    }
}

// ---------------------------------------------------------------------------
extern "C" void kernel_launch(void* const* d_in, const int* in_sizes, int n_in,
                              void* d_out, int out_size)
{
    const float* x  = (const float*)d_in[0];
    const float* Wq = (const float*)d_in[1];
    const float* bq = (const float*)d_in[2];
    const float* Wk = (const float*)d_in[3];
    const float* bk = (const float*)d_in[4];
    const float* Wv = (const float*)d_in[5];
    const float* bv = (const float*)d_in[6];
    float* out = (float*)d_out;

    dim3 ggrid(B_ * HW_ / 64, 3, 1);
    qkv_gemm<<<ggrid, 256>>>(x, Wq, bq, Wk, bk, Wv, bv);

    dim3 agrid(W_ / TW, H_ / TH, B_);
    local_attn<<<agrid, 256>>>(out);
}